// round 3
// baseline (speedup 1.0000x reference)
#include <cuda_runtime.h>
#include <stdint.h>

// ---------------------------------------------------------------------------
// SymmetricRBM: CD-k loss with symmetrized free energy, bit-exact JAX threefry.
// ---------------------------------------------------------------------------

#define PARTITIONABLE 1   // jax_threefry_partitionable (default True since jax 0.4.36)

#define Bn 8192
#define Vn 1024
#define Hn 1024
#define KSTEPS 10

// ------------------------- scratch (device globals) -------------------------
__device__ float    g_v[Bn * Vn];     // chain state v
__device__ float    g_vbr[Bn * Vn];   // v_branch
__device__ float    g_s[Bn * Hn];     // pre-activations / vW scratch
__device__ float    g_h[Bn * Hn];     // hidden samples
__device__ float    g_a[Bn * Vn];     // h @ W^T
__device__ float    g_Wt[Hn * Vn];    // W transpose
__device__ float    g_wcol[Hn];       // W.sum(axis=0)
__device__ float    g_u[Bn];          // flip indicator u
__device__ float    g_bsum;           // b.sum()
__device__ uint32_t g_keys[2 + 6 * KSTEPS];
__device__ double   g_acc[2];         // sum F(v_data), sum F(v_model)

// ------------------------------ threefry2x32 -------------------------------
__device__ __forceinline__ uint32_t rotl_(uint32_t x, int r) {
    return (x << r) | (x >> (32 - r));
}

__device__ __forceinline__ void tf2x32(uint32_t k0, uint32_t k1,
                                       uint32_t x0, uint32_t x1,
                                       uint32_t& o0, uint32_t& o1) {
    uint32_t ks2 = k0 ^ k1 ^ 0x1BD11BDAu;
    x0 += k0; x1 += k1;
#define TF_R4(a,b,c,d) \
    x0 += x1; x1 = rotl_(x1, a); x1 ^= x0; \
    x0 += x1; x1 = rotl_(x1, b); x1 ^= x0; \
    x0 += x1; x1 = rotl_(x1, c); x1 ^= x0; \
    x0 += x1; x1 = rotl_(x1, d); x1 ^= x0;
    TF_R4(13, 15, 26, 6)
    x0 += k1;  x1 += ks2 + 1u;
    TF_R4(17, 29, 16, 24)
    x0 += ks2; x1 += k0 + 2u;
    TF_R4(13, 15, 26, 6)
    x0 += k0;  x1 += k1 + 3u;
    TF_R4(17, 29, 16, 24)
    x0 += k1;  x1 += ks2 + 4u;
    TF_R4(13, 15, 26, 6)
    x0 += ks2; x1 += k0 + 5u;
#undef TF_R4
    o0 = x0; o1 = x1;
}

// random bits for flat index i in an array of n elements
__device__ __forceinline__ uint32_t rbits(uint32_t ka, uint32_t kb,
                                          uint32_t i, uint32_t n) {
#if PARTITIONABLE
    uint32_t o0, o1;
    tf2x32(ka, kb, 0u, i, o0, o1);
    return o0 ^ o1;
#else
    uint32_t half = n >> 1, o0, o1;
    if (i < half) { tf2x32(ka, kb, i, i + half, o0, o1); return o0; }
    else          { tf2x32(ka, kb, i - half, i, o0, o1); return o1; }
#endif
}

__device__ __forceinline__ float u01(uint32_t bits) {
    // JAX uniform: bitcast((bits>>9) | 0x3f800000) - 1.0
    return __uint_as_float((bits >> 9) | 0x3F800000u) - 1.0f;
}

__device__ __forceinline__ float sigmoidf_(float x) {
    return 1.0f / (1.0f + expf(-x));
}

__device__ __forceinline__ float softplusf_(float x) {
    return fmaxf(x, 0.0f) + log1pf(expf(-fabsf(x)));
}

__device__ __forceinline__ float warpSum(float v) {
#pragma unroll
    for (int o = 16; o; o >>= 1) v += __shfl_down_sync(0xffffffffu, v, o);
    return v;
}

// ------------------------------ key derivation -----------------------------
__global__ void k_keys(const int* __restrict__ seed) {
    if (threadIdx.x != 0 || blockIdx.x != 0) return;
    uint32_t ck0 = 0u;                       // hi word of int32 seed (jax: 0)
    uint32_t ck1 = (uint32_t)seed[0];
    uint32_t a, b, o0, o1;
#if PARTITIONABLE
    // split(key): child_i = cipher(key, (0, i)); key = child0, k_u0 = child1
    tf2x32(ck0, ck1, 0u, 0u, o0, o1);
    tf2x32(ck0, ck1, 0u, 1u, a, b);
    g_keys[0] = a; g_keys[1] = b;
    ck0 = o0; ck1 = o1;
    for (int t = 0; t < KSTEPS; t++) {
        uint32_t n0, n1;
        tf2x32(ck0, ck1, 0u, 0u, n0, n1);
        tf2x32(ck0, ck1, 0u, 1u, a, b); g_keys[2 + 6*t + 0] = a; g_keys[2 + 6*t + 1] = b;
        tf2x32(ck0, ck1, 0u, 2u, a, b); g_keys[2 + 6*t + 2] = a; g_keys[2 + 6*t + 3] = b;
        tf2x32(ck0, ck1, 0u, 3u, a, b); g_keys[2 + 6*t + 4] = a; g_keys[2 + 6*t + 5] = b;
        ck0 = n0; ck1 = n1;
    }
#else
    // original split: counts iota(2n), halves, keys[j]=(out[2j],out[2j+1])
    uint32_t a0, a1, b0, b1;
    tf2x32(ck0, ck1, 0u, 2u, a0, b0);
    tf2x32(ck0, ck1, 1u, 3u, a1, b1);
    g_keys[0] = b0; g_keys[1] = b1;     // k_u0
    ck0 = a0; ck1 = a1;                 // new key
    for (int t = 0; t < KSTEPS; t++) {
        uint32_t q0[4], q1[4];
        for (int i = 0; i < 4; i++)
            tf2x32(ck0, ck1, (uint32_t)i, (uint32_t)(i + 4), q0[i], q1[i]);
        g_keys[2 + 6*t + 0] = q0[2]; g_keys[2 + 6*t + 1] = q0[3];  // k1
        g_keys[2 + 6*t + 2] = q1[0]; g_keys[2 + 6*t + 3] = q1[1];  // k2
        g_keys[2 + 6*t + 4] = q1[2]; g_keys[2 + 6*t + 5] = q1[3];  // k3
        ck0 = q0[0]; ck1 = q0[1];
    }
#endif
}

// ------------------------------ setup kernels ------------------------------
__global__ void k_copy(const float* __restrict__ src, float* __restrict__ dst, int n4) {
    int i = blockIdx.x * blockDim.x + threadIdx.x;
    if (i < n4) ((float4*)dst)[i] = ((const float4*)src)[i];
}

__global__ void k_transpose(const float* __restrict__ W, float* __restrict__ Wt) {
    __shared__ float tile[32][33];
    int x = blockIdx.x * 32 + threadIdx.x;
    int y0 = blockIdx.y * 32;
    for (int j = threadIdx.y; j < 32; j += 8)
        tile[j][threadIdx.x] = W[(size_t)(y0 + j) * Hn + x];
    __syncthreads();
    int x2 = blockIdx.y * 32 + threadIdx.x;
    int y2 = blockIdx.x * 32;
    for (int j = threadIdx.y; j < 32; j += 8)
        Wt[(size_t)(y2 + j) * Vn + x2] = tile[threadIdx.x][j];
}

__global__ void k_wcol(const float* __restrict__ W) {
    int h = blockIdx.x * 256 + threadIdx.x;
    if (h < Hn) {
        float s = 0.0f;
        for (int v = 0; v < Vn; v++) s += W[(size_t)v * Hn + h];
        g_wcol[h] = s;
    }
}

__global__ void k_bsum(const float* __restrict__ b) {
    float s = 0.0f;
    for (int j = threadIdx.x; j < Vn; j += 256) s += b[j];
    __shared__ float sh[8];
    float w = warpSum(s);
    if ((threadIdx.x & 31) == 0) sh[threadIdx.x >> 5] = w;
    __syncthreads();
    if (threadIdx.x == 0) {
        float t = 0.0f;
        for (int k = 0; k < 8; k++) t += sh[k];
        g_bsum = t;
        g_acc[0] = 0.0;
        g_acc[1] = 0.0;
    }
}

__global__ void k_u0() {
    int i = blockIdx.x * 256 + threadIdx.x;
    if (i < Bn) {
        uint32_t bits = rbits(g_keys[0], g_keys[1], (uint32_t)i, Bn);
        g_u[i] = (u01(bits) < 0.5f) ? 1.0f : 0.0f;
    }
}

// ------------------------------ Gibbs kernels ------------------------------
__global__ void k_vbranch() {
    int i = blockIdx.x * 256 + threadIdx.x;
    float u = g_u[i >> 10];      // Vn = 1024
    float v = g_v[i];
    g_vbr[i] = (u != 0.0f) ? v : 1.0f - v;
}

__global__ void k_hidden(const float* __restrict__ c, int koff) {
    int i = blockIdx.x * 256 + threadIdx.x;
    uint32_t ka = g_keys[koff], kb = g_keys[koff + 1];
    float p = sigmoidf_(g_s[i] + c[i & (Hn - 1)]);
    uint32_t bits = rbits(ka, kb, (uint32_t)i, (uint32_t)(Bn * Hn));
    g_h[i] = (u01(bits) < p) ? 1.0f : 0.0f;
}

__global__ void k_dE(const float* __restrict__ bb, int koff) {
    int row = blockIdx.x;
    const float* arow = g_a + (size_t)row * Vn;
    const float* vrow = g_v + (size_t)row * Vn;
    float asum = 0.0f, va = 0.0f, vb = 0.0f;
    for (int j = threadIdx.x; j < Vn; j += 256) {
        float av = arow[j], vv = vrow[j];
        asum += av; va += vv * av; vb += vv * bb[j];
    }
    __shared__ float sh[3][8];
    float w0 = warpSum(asum), w1 = warpSum(va), w2 = warpSum(vb);
    int lane = threadIdx.x & 31, wid = threadIdx.x >> 5;
    if (lane == 0) { sh[0][wid] = w0; sh[1][wid] = w1; sh[2][wid] = w2; }
    __syncthreads();
    if (threadIdx.x == 0) {
        float A = 0, Va = 0, Vb = 0;
        for (int k = 0; k < 8; k++) { A += sh[0][k]; Va += sh[1][k]; Vb += sh[2][k]; }
        float dE = -g_bsum - A + 2.0f * Vb + 2.0f * Va;
        float pu = sigmoidf_(dE);
        uint32_t bits = rbits(g_keys[koff], g_keys[koff + 1], (uint32_t)row, Bn);
        g_u[row] = (u01(bits) < pu) ? 1.0f : 0.0f;
    }
}

__global__ void k_vupd(const float* __restrict__ bb, int koff) {
    int i = blockIdx.x * 256 + threadIdx.x;
    uint32_t ka = g_keys[koff], kb = g_keys[koff + 1];
    float p = sigmoidf_(g_a[i] + bb[i & (Vn - 1)]);
    uint32_t bits = rbits(ka, kb, (uint32_t)i, (uint32_t)(Bn * Vn));
    float vn = (u01(bits) < p) ? 1.0f : 0.0f;
    float un = g_u[i >> 10];
    g_v[i] = (un != 0.0f) ? vn : 1.0f - vn;
}

// ------------------------------ free energy --------------------------------
__global__ void k_fe(const float* __restrict__ v, const float* __restrict__ bb,
                     const float* __restrict__ cc, int accIdx) {
    int row = blockIdx.x;
    const float* srow = g_s + (size_t)row * Hn;
    const float* vrow = v + (size_t)row * Vn;
    float sp1 = 0.0f, sp2 = 0.0f, vb = 0.0f;
    for (int j = threadIdx.x; j < Hn; j += 256) {
        float s = srow[j];
        sp1 += softplusf_(s + cc[j]);
        sp2 += softplusf_(g_wcol[j] - s + cc[j]);
    }
    for (int j = threadIdx.x; j < Vn; j += 256) vb += vrow[j] * bb[j];
    __shared__ float sh[3][8];
    float w0 = warpSum(sp1), w1 = warpSum(sp2), w2 = warpSum(vb);
    int lane = threadIdx.x & 31, wid = threadIdx.x >> 5;
    if (lane == 0) { sh[0][wid] = w0; sh[1][wid] = w1; sh[2][wid] = w2; }
    __syncthreads();
    if (threadIdx.x == 0) {
        float S1 = 0, S2 = 0, VB = 0;
        for (int k = 0; k < 8; k++) { S1 += sh[0][k]; S2 += sh[1][k]; VB += sh[2][k]; }
        float nfn = VB - S1;                       // negF_normal
        float nff = (g_bsum - VB) - S2;            // negF_flip
        float m = fmaxf(nfn, nff);
        float F = -(m + log1pf(expf(fminf(nfn, nff) - m)));
        atomicAdd(&g_acc[accIdx], (double)F);
    }
}

__global__ void k_final(float* __restrict__ out) {
    if (threadIdx.x == 0 && blockIdx.x == 0)
        out[0] = (float)((g_acc[0] - g_acc[1]) * (1.0 / (double)Bn));
}

// ------------------------------ SGEMM 8192x1024x1024 -----------------------
// C[8192,1024] = A[8192,1024] @ B[1024,1024], all row-major fp32.
__global__ __launch_bounds__(256) void k_gemm(const float* __restrict__ A,
                                              const float* __restrict__ Bm,
                                              float* __restrict__ C) {
    const int K = 1024, N = 1024;
    __shared__ float As[8][128];
    __shared__ float Bs[8][128];
    const int cRow = blockIdx.y;   // M tile (128 rows)
    const int cCol = blockIdx.x;   // N tile (128 cols)
    const int tid = threadIdx.x;
    const int trow = tid >> 4;     // 0..15
    const int tcol = tid & 15;     // 0..15
    const int aRow = tid >> 1;          // 0..127
    const int aCol = (tid & 1) << 2;    // 0 or 4
    const int bRow = tid >> 5;          // 0..7
    const int bCol = (tid & 31) << 2;   // 0..124

    const float* Ablk = A + (size_t)cRow * 128 * K;
    const float* Bblk = Bm + (size_t)cCol * 128;

    float acc[8][8];
#pragma unroll
    for (int m = 0; m < 8; m++)
#pragma unroll
        for (int n = 0; n < 8; n++) acc[m][n] = 0.0f;

    for (int k0 = 0; k0 < K; k0 += 8) {
        float4 a4 = *(const float4*)(Ablk + (size_t)aRow * K + k0 + aCol);
        As[aCol + 0][aRow] = a4.x;
        As[aCol + 1][aRow] = a4.y;
        As[aCol + 2][aRow] = a4.z;
        As[aCol + 3][aRow] = a4.w;
        float4 b4 = *(const float4*)(Bblk + (size_t)(k0 + bRow) * N + bCol);
        *(float4*)&Bs[bRow][bCol] = b4;
        __syncthreads();
#pragma unroll
        for (int kk = 0; kk < 8; kk++) {
            float regM[8], regN[8];
            float4 m0 = *(const float4*)&As[kk][trow * 8];
            float4 m1 = *(const float4*)&As[kk][trow * 8 + 4];
            regM[0] = m0.x; regM[1] = m0.y; regM[2] = m0.z; regM[3] = m0.w;
            regM[4] = m1.x; regM[5] = m1.y; regM[6] = m1.z; regM[7] = m1.w;
            float4 n0 = *(const float4*)&Bs[kk][tcol * 8];
            float4 n1 = *(const float4*)&Bs[kk][tcol * 8 + 4];
            regN[0] = n0.x; regN[1] = n0.y; regN[2] = n0.z; regN[3] = n0.w;
            regN[4] = n1.x; regN[5] = n1.y; regN[6] = n1.z; regN[7] = n1.w;
#pragma unroll
            for (int m = 0; m < 8; m++)
#pragma unroll
                for (int n = 0; n < 8; n++)
                    acc[m][n] += regM[m] * regN[n];
        }
        __syncthreads();
    }

    float* Cblk = C + (size_t)(cRow * 128 + trow * 8) * N + cCol * 128 + tcol * 8;
#pragma unroll
    for (int m = 0; m < 8; m++) {
        float4 r0 = make_float4(acc[m][0], acc[m][1], acc[m][2], acc[m][3]);
        float4 r1 = make_float4(acc[m][4], acc[m][5], acc[m][6], acc[m][7]);
        *(float4*)(Cblk + (size_t)m * N)     = r0;
        *(float4*)(Cblk + (size_t)m * N + 4) = r1;
    }
}

// ------------------------------ launch -------------------------------------
extern "C" void kernel_launch(void* const* d_in, const int* in_sizes, int n_in,
                              void* d_out, int out_size) {
    const float* v_data = (const float*)d_in[0];
    const float* W      = (const float*)d_in[1];
    const float* b      = (const float*)d_in[2];
    const float* c      = (const float*)d_in[3];
    const int*   seed   = (const int*)d_in[4];
    float* out = (float*)d_out;

    float *p_v, *p_vbr, *p_s, *p_h, *p_a, *p_Wt;
    cudaGetSymbolAddress((void**)&p_v,   g_v);
    cudaGetSymbolAddress((void**)&p_vbr, g_vbr);
    cudaGetSymbolAddress((void**)&p_s,   g_s);
    cudaGetSymbolAddress((void**)&p_h,   g_h);
    cudaGetSymbolAddress((void**)&p_a,   g_a);
    cudaGetSymbolAddress((void**)&p_Wt,  g_Wt);

    dim3 ggrid(Vn / 128, Bn / 128);   // (8, 64)

    k_keys<<<1, 32>>>(seed);
    k_copy<<<(Bn * Vn / 4 + 255) / 256, 256>>>(v_data, p_v, Bn * Vn / 4);
    k_transpose<<<dim3(Hn / 32, Vn / 32), dim3(32, 8)>>>(W, p_Wt);
    k_wcol<<<Hn / 256, 256>>>(W);
    k_bsum<<<1, 256>>>(b);
    k_u0<<<Bn / 256, 256>>>();

    for (int t = 0; t < KSTEPS; t++) {
        int koff = 2 + 6 * t;
        k_vbranch<<<Bn * Vn / 256, 256>>>();
        k_gemm<<<ggrid, 256>>>(p_vbr, W, p_s);           // s = v_branch @ W
        k_hidden<<<Bn * Hn / 256, 256>>>(c, koff);       // h ~ bern(sigmoid(s+c))
        k_gemm<<<ggrid, 256>>>(p_h, p_Wt, p_a);          // a = h @ W^T
        k_dE<<<Bn, 256>>>(b, koff + 2);                  // u_new ~ bern(sigmoid(dE))
        k_vupd<<<Bn * Vn / 256, 256>>>(b, koff + 4);     // v ~ sym-flip(bern(sigmoid(a+b)))
    }

    k_gemm<<<ggrid, 256>>>(v_data, W, p_s);
    k_fe<<<Bn, 256>>>(v_data, b, c, 0);
    k_gemm<<<ggrid, 256>>>(p_v, W, p_s);
    k_fe<<<Bn, 256>>>(p_v, b, c, 1);
    k_final<<<1, 1>>>(out);
}

// round 4
// speedup vs baseline: 2.5422x; 2.5422x over previous
#include <cuda_runtime.h>
#include <cuda_bf16.h>
#include <stdint.h>

#define Bn 8192
#define Vn 1024
#define KSTEPS 10

__device__ __nv_bfloat16 g_A1[Bn * Vn];    // GEMM1 A (v_branch / v_new)
__device__ __nv_bfloat16 g_h16[Bn * Vn];   // hidden samples
__device__ __nv_bfloat16 g_v16[Bn * Vn];   // chain v (flipped)
__device__ __nv_bfloat16 g_vd16[Bn * Vn];  // v_data
__device__ __nv_bfloat16 g_B1[1024 * 2048]; // [h][v]: W^T hi | lo
__device__ __nv_bfloat16 g_B2[1024 * 2048]; // [v][h]: W hi | lo
__device__ float    g_s[Bn * Vn];
__device__ float    g_a[Bn * Vn];
__device__ float    g_wcol[1024];
__device__ float    g_u[Bn];
__device__ float    g_bsum;
__device__ uint32_t g_keys[2 + 6 * KSTEPS];
__device__ double   g_acc[2];

// ------------------------------ threefry -----------------------------------
__device__ __forceinline__ uint32_t rotl_(uint32_t x, int r) {
    return (x << r) | (x >> (32 - r));
}
__device__ __forceinline__ void tf2x32(uint32_t k0, uint32_t k1, uint32_t x0,
                                       uint32_t x1, uint32_t& o0, uint32_t& o1) {
    uint32_t ks2 = k0 ^ k1 ^ 0x1BD11BDAu;
    x0 += k0; x1 += k1;
#define TF_R4(a,b,c,d) \
    x0 += x1; x1 = rotl_(x1, a); x1 ^= x0; \
    x0 += x1; x1 = rotl_(x1, b); x1 ^= x0; \
    x0 += x1; x1 = rotl_(x1, c); x1 ^= x0; \
    x0 += x1; x1 = rotl_(x1, d); x1 ^= x0;
    TF_R4(13, 15, 26, 6)
    x0 += k1;  x1 += ks2 + 1u;
    TF_R4(17, 29, 16, 24)
    x0 += ks2; x1 += k0 + 2u;
    TF_R4(13, 15, 26, 6)
    x0 += k0;  x1 += k1 + 3u;
    TF_R4(17, 29, 16, 24)
    x0 += k1;  x1 += ks2 + 4u;
    TF_R4(13, 15, 26, 6)
    x0 += ks2; x1 += k0 + 5u;
#undef TF_R4
    o0 = x0; o1 = x1;
}
__device__ __forceinline__ uint32_t rbits(uint32_t ka, uint32_t kb, uint32_t i) {
    uint32_t o0, o1;
    tf2x32(ka, kb, 0u, i, o0, o1);
    return o0 ^ o1;
}
__device__ __forceinline__ float u01(uint32_t b) {
    return __uint_as_float((b >> 9) | 0x3F800000u) - 1.0f;
}
__device__ __forceinline__ float sigm(float x) { return 1.0f / (1.0f + expf(-x)); }
__device__ __forceinline__ float softp(float x) {
    return fmaxf(x, 0.0f) + log1pf(expf(-fabsf(x)));
}
__device__ __forceinline__ float warpSum(float v) {
#pragma unroll
    for (int o = 16; o; o >>= 1) v += __shfl_down_sync(0xffffffffu, v, o);
    return v;
}

// ------------------------------ mma helpers --------------------------------
__device__ __forceinline__ uint32_t cvta_s(const void* p) {
    uint32_t a;
    asm("{.reg .u64 t; cvta.to.shared.u64 t, %1; cvt.u32.u64 %0, t;}" : "=r"(a) : "l"(p));
    return a;
}
__device__ __forceinline__ void ldm4(uint32_t& r0, uint32_t& r1, uint32_t& r2,
                                     uint32_t& r3, uint32_t a) {
    asm volatile("ldmatrix.sync.aligned.m8n8.x4.shared.b16 {%0,%1,%2,%3},[%4];"
                 : "=r"(r0), "=r"(r1), "=r"(r2), "=r"(r3) : "r"(a));
}
__device__ __forceinline__ void mma16816(float* d, const uint32_t* a, const uint32_t* b) {
    asm volatile(
        "mma.sync.aligned.m16n8k16.row.col.f32.bf16.bf16.f32 "
        "{%0,%1,%2,%3},{%4,%5,%6,%7},{%8,%9},{%0,%1,%2,%3};"
        : "+f"(d[0]), "+f"(d[1]), "+f"(d[2]), "+f"(d[3])
        : "r"(a[0]), "r"(a[1]), "r"(a[2]), "r"(a[3]), "r"(b[0]), "r"(b[1]));
}
__device__ __forceinline__ void cpa16(uint32_t s, const void* g) {
    asm volatile("cp.async.cg.shared.global [%0],[%1],16;" :: "r"(s), "l"(g));
}
#define CPCOMMIT() asm volatile("cp.async.commit_group;")
#define CPWAIT(n)  asm volatile("cp.async.wait_group %0;" :: "n"(n) : "memory")

// ------------------------- GEMM: C=A[8192,1024dup2048]@B[1024,2048]^T ------
// MODE 0: sample hidden -> g_h16.  MODE 1: write fp32 to Cf.
template <int MODE>
__global__ __launch_bounds__(256, 2) void k_mma(const __nv_bfloat16* __restrict__ A,
                                                const __nv_bfloat16* __restrict__ Bm,
                                                float* __restrict__ Cf,
                                                const float* __restrict__ bias, int koff) {
    __shared__ __nv_bfloat16 sm[2 * 20480 / 2];
    const int tid = threadIdx.x, lane = tid & 31, wid = tid >> 5;
    const int wm = wid >> 1, wn = wid & 1;
    const int bM = blockIdx.y, bN = blockIdx.x;
    const uint32_t sbase = cvta_s(sm);

    const int lrow = tid >> 1, lc = (tid & 1) * 2;       // gmem->smem
    const __nv_bfloat16* aG = A + (size_t)(bM * 128 + lrow) * 1024;
    const __nv_bfloat16* bG = Bm + (size_t)(bN * 128 + lrow) * 2048 + lc * 8;
    const uint32_t dA = sbase + lrow * 80 + lc * 16;
    const uint32_t dB = dA + 10240;

    // ldmatrix source offsets
    const int arow = wm * 32 + (lane & 7) + ((lane & 8) ? 8 : 0);
    const int acol = ((lane & 16) ? 8 : 0);
    const int brow = wn * 64 + (lane & 7) + ((lane & 16) ? 8 : 0);
    const int bcol = ((lane & 8) ? 8 : 0);

    float acc[2][8][4];
#pragma unroll
    for (int m = 0; m < 2; m++)
#pragma unroll
        for (int n = 0; n < 8; n++)
#pragma unroll
            for (int q = 0; q < 4; q++) acc[m][n][q] = 0.0f;

#define LOAD(st, k0) { \
    cpa16(dA + (st) * 20480,      aG + (((k0) + lc * 8) & 1023));     \
    cpa16(dA + (st) * 20480 + 16, aG + (((k0) + lc * 8 + 8) & 1023)); \
    cpa16(dB + (st) * 20480,      bG + (k0));                         \
    cpa16(dB + (st) * 20480 + 16, bG + (k0) + 8);                     \
    CPCOMMIT(); }

    LOAD(0, 0)
    for (int it = 0; it < 64; it++) {
        int st = it & 1;
        if (it < 63) { LOAD(st ^ 1, (it + 1) * 32) CPWAIT(1); }
        else CPWAIT(0);
        __syncthreads();
        uint32_t ab = sbase + st * 20480;
#pragma unroll
        for (int ks = 0; ks < 32; ks += 16) {
            uint32_t Af[2][4], Bf[8][2];
#pragma unroll
            for (int mt = 0; mt < 2; mt++)
                ldm4(Af[mt][0], Af[mt][1], Af[mt][2], Af[mt][3],
                     ab + (arow + mt * 16) * 80 + (ks + acol) * 2);
#pragma unroll
            for (int nb = 0; nb < 4; nb++)
                ldm4(Bf[2 * nb][0], Bf[2 * nb][1], Bf[2 * nb + 1][0], Bf[2 * nb + 1][1],
                     ab + 10240 + (brow + nb * 16) * 80 + (ks + bcol) * 2);
#pragma unroll
            for (int mt = 0; mt < 2; mt++)
#pragma unroll
                for (int nf = 0; nf < 8; nf++) mma16816(acc[mt][nf], Af[mt], Bf[nf]);
        }
        __syncthreads();
    }

    // epilogue
    uint32_t ka = 0, kb = 0;
    if (MODE == 0) { ka = g_keys[koff]; kb = g_keys[koff + 1]; }
#pragma unroll
    for (int mt = 0; mt < 2; mt++) {
        int R0 = bM * 128 + wm * 32 + mt * 16 + (lane >> 2);
#pragma unroll
        for (int nf = 0; nf < 8; nf++) {
            int C0 = bN * 128 + wn * 64 + nf * 8 + (lane & 3) * 2;
            uint32_t i0 = (uint32_t)R0 * 1024u + (uint32_t)C0;
            uint32_t i1 = i0 + 8 * 1024;
            if (MODE == 0) {
                float b0 = bias[C0], b1 = bias[C0 + 1];
                uint32_t p;
                p  = (u01(rbits(ka, kb, i0))     < sigm(acc[mt][nf][0] + b0)) ? 0x3F80u : 0u;
                p |= (u01(rbits(ka, kb, i0 + 1)) < sigm(acc[mt][nf][1] + b1)) ? 0x3F800000u : 0u;
                *(uint32_t*)(g_h16 + i0) = p;
                p  = (u01(rbits(ka, kb, i1))     < sigm(acc[mt][nf][2] + b0)) ? 0x3F80u : 0u;
                p |= (u01(rbits(ka, kb, i1 + 1)) < sigm(acc[mt][nf][3] + b1)) ? 0x3F800000u : 0u;
                *(uint32_t*)(g_h16 + i1) = p;
            } else {
                *(float2*)(Cf + i0) = make_float2(acc[mt][nf][0], acc[mt][nf][1]);
                *(float2*)(Cf + i1) = make_float2(acc[mt][nf][2], acc[mt][nf][3]);
            }
        }
    }
}

// ------------------------------ small kernels ------------------------------
__global__ void k_keys(const int* __restrict__ seed) {
    if (threadIdx.x != 0 || blockIdx.x != 0) return;
    uint32_t ck0 = 0u, ck1 = (uint32_t)seed[0], a, b, o0, o1;
    tf2x32(ck0, ck1, 0u, 0u, o0, o1);
    tf2x32(ck0, ck1, 0u, 1u, a, b);
    g_keys[0] = a; g_keys[1] = b; ck0 = o0; ck1 = o1;
    for (int t = 0; t < KSTEPS; t++) {
        uint32_t n0, n1;
        tf2x32(ck0, ck1, 0u, 0u, n0, n1);
        tf2x32(ck0, ck1, 0u, 1u, a, b); g_keys[2+6*t+0] = a; g_keys[2+6*t+1] = b;
        tf2x32(ck0, ck1, 0u, 2u, a, b); g_keys[2+6*t+2] = a; g_keys[2+6*t+3] = b;
        tf2x32(ck0, ck1, 0u, 3u, a, b); g_keys[2+6*t+4] = a; g_keys[2+6*t+5] = b;
        ck0 = n0; ck1 = n1;
    }
}

__global__ void k_cvt(const float* __restrict__ vd) {
    int i = blockIdx.x * 256 + threadIdx.x;
    __nv_bfloat16 x = __float2bfloat16(vd[i]);
    g_vd16[i] = x; g_v16[i] = x;
}

__global__ void k_split2(const float* __restrict__ W) {
    int i = blockIdx.x * 256 + threadIdx.x;
    float w = W[i];
    __nv_bfloat16 hi = __float2bfloat16(w);
    int v = i >> 10, k = i & 1023;
    g_B2[(size_t)v * 2048 + k] = hi;
    g_B2[(size_t)v * 2048 + 1024 + k] = __float2bfloat16(w - __bfloat162float(hi));
}

__global__ void k_split1(const float* __restrict__ W) {
    __shared__ float t[32][33];
    int x = blockIdx.x * 32 + threadIdx.x, y0 = blockIdx.y * 32;
    for (int j = threadIdx.y; j < 32; j += 8)
        t[j][threadIdx.x] = W[(size_t)(y0 + j) * 1024 + x];
    __syncthreads();
    for (int j = threadIdx.y; j < 32; j += 8) {
        float w = t[threadIdx.x][j];
        int h = blockIdx.x * 32 + j, v = y0 + threadIdx.x;
        __nv_bfloat16 hi = __float2bfloat16(w);
        g_B1[(size_t)h * 2048 + v] = hi;
        g_B1[(size_t)h * 2048 + 1024 + v] = __float2bfloat16(w - __bfloat162float(hi));
    }
}

__global__ void k_wcol(const float* __restrict__ W) {
    int h = blockIdx.x * 256 + threadIdx.x;
    float s = 0.0f;
    for (int v = 0; v < 1024; v++) s += W[(size_t)v * 1024 + h];
    g_wcol[h] = s;
}

__global__ void k_bsum(const float* __restrict__ b) {
    float s = 0.0f;
    for (int j = threadIdx.x; j < 1024; j += 256) s += b[j];
    __shared__ float sh[8];
    float w = warpSum(s);
    if ((threadIdx.x & 31) == 0) sh[threadIdx.x >> 5] = w;
    __syncthreads();
    if (threadIdx.x == 0) {
        float t = 0.0f;
        for (int k = 0; k < 8; k++) t += sh[k];
        g_bsum = t; g_acc[0] = 0.0; g_acc[1] = 0.0;
    }
}

__global__ void k_u0() {
    int i = blockIdx.x * 256 + threadIdx.x;
    g_u[i] = (u01(rbits(g_keys[0], g_keys[1], (uint32_t)i)) < 0.5f) ? 1.0f : 0.0f;
}

__global__ void k_vbranch0() {
    int i = blockIdx.x * 256 + threadIdx.x;
    float u = g_u[i >> 10];
    float v = __bfloat162float(g_v16[i]);
    g_A1[i] = __float2bfloat16((u != 0.0f) ? v : 1.0f - v);
}

__global__ void k_dE(const float* __restrict__ bb, int koff) {
    int row = blockIdx.x;
    const float* arow = g_a + (size_t)row * 1024;
    const __nv_bfloat16* vrow = g_v16 + (size_t)row * 1024;
    float asum = 0.0f, va = 0.0f, vb = 0.0f;
    for (int j = threadIdx.x; j < 1024; j += 256) {
        float av = arow[j], vv = __bfloat162float(vrow[j]);
        asum += av; va += vv * av; vb += vv * bb[j];
    }
    __shared__ float sh[3][8];
    float w0 = warpSum(asum), w1 = warpSum(va), w2 = warpSum(vb);
    int lane = threadIdx.x & 31, wd = threadIdx.x >> 5;
    if (lane == 0) { sh[0][wd] = w0; sh[1][wd] = w1; sh[2][wd] = w2; }
    __syncthreads();
    if (threadIdx.x == 0) {
        float A = 0, Va = 0, Vb = 0;
        for (int k = 0; k < 8; k++) { A += sh[0][k]; Va += sh[1][k]; Vb += sh[2][k]; }
        float dE = -g_bsum - A + 2.0f * Vb + 2.0f * Va;
        g_u[row] = (u01(rbits(g_keys[koff], g_keys[koff + 1], (uint32_t)row)) < sigm(dE))
                   ? 1.0f : 0.0f;
    }
}

__global__ void k_vupd(const float* __restrict__ bb, int koff) {
    int i = blockIdx.x * 256 + threadIdx.x;
    uint32_t ka = g_keys[koff], kb = g_keys[koff + 1];
    float p = sigm(g_a[i] + bb[i & 1023]);
    float vn = (u01(rbits(ka, kb, (uint32_t)i)) < p) ? 1.0f : 0.0f;
    g_A1[i] = __float2bfloat16(vn);
    float un = g_u[i >> 10];
    g_v16[i] = __float2bfloat16((un != 0.0f) ? vn : 1.0f - vn);
}

__global__ void k_fe(const __nv_bfloat16* __restrict__ v, const float* __restrict__ bb,
                     const float* __restrict__ cc, int accIdx) {
    int row = blockIdx.x;
    const float* srow = g_s + (size_t)row * 1024;
    const __nv_bfloat16* vrow = v + (size_t)row * 1024;
    float sp1 = 0.0f, sp2 = 0.0f, vb = 0.0f;
    for (int j = threadIdx.x; j < 1024; j += 256) {
        float s = srow[j];
        sp1 += softp(s + cc[j]);
        sp2 += softp(g_wcol[j] - s + cc[j]);
        vb += __bfloat162float(vrow[j]) * bb[j];
    }
    __shared__ float sh[3][8];
    float w0 = warpSum(sp1), w1 = warpSum(sp2), w2 = warpSum(vb);
    int lane = threadIdx.x & 31, wd = threadIdx.x >> 5;
    if (lane == 0) { sh[0][wd] = w0; sh[1][wd] = w1; sh[2][wd] = w2; }
    __syncthreads();
    if (threadIdx.x == 0) {
        float S1 = 0, S2 = 0, VB = 0;
        for (int k = 0; k < 8; k++) { S1 += sh[0][k]; S2 += sh[1][k]; VB += sh[2][k]; }
        float nfn = VB - S1, nff = (g_bsum - VB) - S2;
        float m = fmaxf(nfn, nff);
        float F = -(m + log1pf(expf(fminf(nfn, nff) - m)));
        atomicAdd(&g_acc[accIdx], (double)F);
    }
}

__global__ void k_final(float* __restrict__ out) {
    if (threadIdx.x == 0 && blockIdx.x == 0)
        out[0] = (float)((g_acc[0] - g_acc[1]) * (1.0 / (double)Bn));
}

// ------------------------------ launch -------------------------------------
extern "C" void kernel_launch(void* const* d_in, const int* in_sizes, int n_in,
                              void* d_out, int out_size) {
    const float* v_data = (const float*)d_in[0];
    const float* W      = (const float*)d_in[1];
    const float* b      = (const float*)d_in[2];
    const float* c      = (const float*)d_in[3];
    const int*   seed   = (const int*)d_in[4];
    float* out = (float*)d_out;

    __nv_bfloat16 *pA1, *pH, *pV, *pVd, *pB1, *pB2;
    float *pS, *pAa;
    cudaGetSymbolAddress((void**)&pA1, g_A1);
    cudaGetSymbolAddress((void**)&pH,  g_h16);
    cudaGetSymbolAddress((void**)&pV,  g_v16);
    cudaGetSymbolAddress((void**)&pVd, g_vd16);
    cudaGetSymbolAddress((void**)&pB1, g_B1);
    cudaGetSymbolAddress((void**)&pB2, g_B2);
    cudaGetSymbolAddress((void**)&pS,  g_s);
    cudaGetSymbolAddress((void**)&pAa, g_a);

    dim3 gg(8, 64);
    k_keys<<<1, 32>>>(seed);
    k_cvt<<<Bn * Vn / 256, 256>>>(v_data);
    k_split2<<<Vn * Vn / 256, 256>>>(W);
    k_split1<<<dim3(32, 32), dim3(32, 8)>>>(W);
    k_wcol<<<4, 256>>>(W);
    k_bsum<<<1, 256>>>(b);
    k_u0<<<Bn / 256, 256>>>();
    k_vbranch0<<<Bn * Vn / 256, 256>>>();

    for (int t = 0; t < KSTEPS; t++) {
        int koff = 2 + 6 * t;
        k_mma<0><<<gg, 256>>>(pA1, pB1, nullptr, c, koff);     // h = sample(vbr @ W)
        k_mma<1><<<gg, 256>>>(pH, pB2, pAa, nullptr, 0);       // a = h @ W^T
        k_dE<<<Bn, 256>>>(b, koff + 2);
        k_vupd<<<Bn * Vn / 256, 256>>>(b, koff + 4);
    }

    k_mma<1><<<gg, 256>>>(pVd, pB1, pS, nullptr, 0);
    k_fe<<<Bn, 256>>>(pVd, b, c, 0);
    k_mma<1><<<gg, 256>>>(pV, pB1, pS, nullptr, 0);
    k_fe<<<Bn, 256>>>(pV, b, c, 1);
    k_final<<<1, 1>>>(out);
}

// round 6
// speedup vs baseline: 3.7109x; 1.4597x over previous
#include <cuda_runtime.h>
#include <cuda_bf16.h>
#include <stdint.h>

#define Bn 8192
#define KSTEPS 10
#define STG 30720            // per-stage smem: A 10240 + Bhi 10240 + Blo 10240
#define SMEM_SZ (3 * STG)

__device__ __nv_bfloat16 g_A1[Bn * 1024];    // GEMM1 A (v_branch / v_new)
__device__ __nv_bfloat16 g_h16[Bn * 1024];   // hidden samples
__device__ __nv_bfloat16 g_v16[Bn * 1024];   // chain v (flipped)
__device__ __nv_bfloat16 g_vd16[Bn * 1024];  // v_data
__device__ __nv_bfloat16 g_B1[1024 * 2048];  // [h][v]: W^T hi | lo
__device__ __nv_bfloat16 g_B2[1024 * 2048];  // [v][h]: W hi | lo
__device__ float    g_s[Bn * 1024];
__device__ float    g_a[Bn * 1024];
__device__ float    g_wcol[1024];
__device__ float    g_u[Bn];
__device__ float    g_bsum;
__device__ uint32_t g_keys[2 + 6 * KSTEPS];
__device__ double   g_acc[2];

// ------------------------------ threefry -----------------------------------
__device__ __forceinline__ uint32_t rotl_(uint32_t x, int r) {
    return (x << r) | (x >> (32 - r));
}
__device__ __forceinline__ void tf2x32(uint32_t k0, uint32_t k1, uint32_t x0,
                                       uint32_t x1, uint32_t& o0, uint32_t& o1) {
    uint32_t ks2 = k0 ^ k1 ^ 0x1BD11BDAu;
    x0 += k0; x1 += k1;
#define TF_R4(a,b,c,d) \
    x0 += x1; x1 = rotl_(x1, a); x1 ^= x0; \
    x0 += x1; x1 = rotl_(x1, b); x1 ^= x0; \
    x0 += x1; x1 = rotl_(x1, c); x1 ^= x0; \
    x0 += x1; x1 = rotl_(x1, d); x1 ^= x0;
    TF_R4(13, 15, 26, 6)
    x0 += k1;  x1 += ks2 + 1u;
    TF_R4(17, 29, 16, 24)
    x0 += ks2; x1 += k0 + 2u;
    TF_R4(13, 15, 26, 6)
    x0 += k0;  x1 += k1 + 3u;
    TF_R4(17, 29, 16, 24)
    x0 += k1;  x1 += ks2 + 4u;
    TF_R4(13, 15, 26, 6)
    x0 += ks2; x1 += k0 + 5u;
#undef TF_R4
    o0 = x0; o1 = x1;
}
__device__ __forceinline__ uint32_t rbits(uint32_t ka, uint32_t kb, uint32_t i) {
    uint32_t o0, o1;
    tf2x32(ka, kb, 0u, i, o0, o1);
    return o0 ^ o1;
}
__device__ __forceinline__ float u01(uint32_t b) {
    return __uint_as_float((b >> 9) | 0x3F800000u) - 1.0f;
}
__device__ __forceinline__ float sigm(float x) { return 1.0f / (1.0f + expf(-x)); }
__device__ __forceinline__ float softp(float x) {
    return fmaxf(x, 0.0f) + log1pf(expf(-fabsf(x)));
}
__device__ __forceinline__ float warpSum(float v) {
#pragma unroll
    for (int o = 16; o; o >>= 1) v += __shfl_down_sync(0xffffffffu, v, o);
    return v;
}

// ------------------------------ mma helpers --------------------------------
__device__ __forceinline__ uint32_t cvta_s(const void* p) {
    uint32_t a;
    asm("{.reg .u64 t; cvta.to.shared.u64 t, %1; cvt.u32.u64 %0, t;}" : "=r"(a) : "l"(p));
    return a;
}
__device__ __forceinline__ void ldm4(uint32_t& r0, uint32_t& r1, uint32_t& r2,
                                     uint32_t& r3, uint32_t a) {
    asm volatile("ldmatrix.sync.aligned.m8n8.x4.shared.b16 {%0,%1,%2,%3},[%4];"
                 : "=r"(r0), "=r"(r1), "=r"(r2), "=r"(r3) : "r"(a));
}
__device__ __forceinline__ void mma16816(float* d, const uint32_t* a, const uint32_t* b) {
    asm volatile(
        "mma.sync.aligned.m16n8k16.row.col.f32.bf16.bf16.f32 "
        "{%0,%1,%2,%3},{%4,%5,%6,%7},{%8,%9},{%0,%1,%2,%3};"
        : "+f"(d[0]), "+f"(d[1]), "+f"(d[2]), "+f"(d[3])
        : "r"(a[0]), "r"(a[1]), "r"(a[2]), "r"(a[3]), "r"(b[0]), "r"(b[1]));
}
__device__ __forceinline__ void cpa16(uint32_t s, const void* g) {
    asm volatile("cp.async.cg.shared.global [%0],[%1],16;" :: "r"(s), "l"(g));
}
#define CPCOMMIT() asm volatile("cp.async.commit_group;")
#define CPWAIT(n)  asm volatile("cp.async.wait_group %0;" :: "n"(n) : "memory")

// -------- GEMM: C[8192,1024] = A[8192,1024] @ (B_hi+B_lo)[1024,1024]^T ------
// B layout: [n][2048] with hi at cols 0..1023, lo at 1024..2047.
// MODE 0: sample hidden -> g_h16 (keys at koff, bias=c).  MODE 1: fp32 -> Cf.
template <int MODE>
__global__ __launch_bounds__(256, 2) void k_mma(const __nv_bfloat16* __restrict__ A,
                                                const __nv_bfloat16* __restrict__ Bm,
                                                float* __restrict__ Cf,
                                                const float* __restrict__ bias, int koff) {
    extern __shared__ char smem[];
    const uint32_t sbase = cvta_s(smem);
    const int tid = threadIdx.x, lane = tid & 31, wid = tid >> 5;
    const int wm = wid >> 1, wn = wid & 1;
    const int bM = blockIdx.y, bN = blockIdx.x;

    // ldmatrix source coords (80B-pitch rows)
    const int arow = wm * 32 + (lane & 7) + ((lane & 8) ? 8 : 0);
    const int acol = ((lane & 16) ? 8 : 0);
    const int brow = wn * 64 + (lane & 7) + ((lane & 16) ? 8 : 0);
    const int bcol = ((lane & 8) ? 8 : 0);

    float acc[2][8][4];
#pragma unroll
    for (int m = 0; m < 2; m++)
#pragma unroll
        for (int n = 0; n < 8; n++)
#pragma unroll
            for (int q = 0; q < 4; q++) acc[m][n][q] = 0.0f;

    // stage load: A 128x32, Bhi 128x32, Blo 128x32 (16B chunks, 2 each/thread)
#define LOADSTAGE(st, k0) { \
    uint32_t db = sbase + (uint32_t)(st) * STG; \
    _Pragma("unroll") \
    for (int it = 0; it < 2; it++) { \
        int idx = it * 256 + tid, r = idx >> 2, c16 = idx & 3; \
        uint32_t so = (uint32_t)(r * 80 + c16 * 16); \
        const __nv_bfloat16* ag = A  + (size_t)(bM * 128 + r) * 1024 + (k0) + c16 * 8; \
        const __nv_bfloat16* bg = Bm + (size_t)(bN * 128 + r) * 2048 + (k0) + c16 * 8; \
        cpa16(db + so, ag); \
        cpa16(db + 10240 + so, bg); \
        cpa16(db + 20480 + so, bg + 1024); \
    } \
    CPCOMMIT(); }

    LOADSTAGE(0, 0)
    LOADSTAGE(1, 32)
    for (int i = 0; i < 32; i++) {
        if (i < 31) CPWAIT(1); else CPWAIT(0);
        __syncthreads();
        uint32_t sb = sbase + (uint32_t)(i % 3) * STG;
#pragma unroll
        for (int ks = 0; ks < 32; ks += 16) {
            uint32_t Af[2][4], Bf[8][2];
#pragma unroll
            for (int mt = 0; mt < 2; mt++)
                ldm4(Af[mt][0], Af[mt][1], Af[mt][2], Af[mt][3],
                     sb + (arow + mt * 16) * 80 + (ks + acol) * 2);
            // hi
#pragma unroll
            for (int nb = 0; nb < 4; nb++)
                ldm4(Bf[2*nb][0], Bf[2*nb][1], Bf[2*nb+1][0], Bf[2*nb+1][1],
                     sb + 10240 + (brow + nb * 16) * 80 + (ks + bcol) * 2);
#pragma unroll
            for (int mt = 0; mt < 2; mt++)
#pragma unroll
                for (int nf = 0; nf < 8; nf++) mma16816(acc[mt][nf], Af[mt], Bf[nf]);
            // lo
#pragma unroll
            for (int nb = 0; nb < 4; nb++)
                ldm4(Bf[2*nb][0], Bf[2*nb][1], Bf[2*nb+1][0], Bf[2*nb+1][1],
                     sb + 20480 + (brow + nb * 16) * 80 + (ks + bcol) * 2);
#pragma unroll
            for (int mt = 0; mt < 2; mt++)
#pragma unroll
                for (int nf = 0; nf < 8; nf++) mma16816(acc[mt][nf], Af[mt], Bf[nf]);
        }
        if (i < 30) { LOADSTAGE((i + 2) % 3, (i + 2) * 32) }
    }
#undef LOADSTAGE

    // epilogue (direct from registers)
    uint32_t ka = 0, kb = 0;
    if (MODE == 0) { ka = g_keys[koff]; kb = g_keys[koff + 1]; }
#pragma unroll
    for (int mt = 0; mt < 2; mt++) {
        int R0 = bM * 128 + wm * 32 + mt * 16 + (lane >> 2);
#pragma unroll
        for (int nf = 0; nf < 8; nf++) {
            int C0 = bN * 128 + wn * 64 + nf * 8 + (lane & 3) * 2;
            uint32_t i0 = (uint32_t)R0 * 1024u + (uint32_t)C0;
            uint32_t i1 = i0 + 8 * 1024;
            if (MODE == 0) {
                float b0 = bias[C0], b1 = bias[C0 + 1];
                uint32_t p;
                p  = (u01(rbits(ka, kb, i0))     < sigm(acc[mt][nf][0] + b0)) ? 0x3F80u : 0u;
                p |= (u01(rbits(ka, kb, i0 + 1)) < sigm(acc[mt][nf][1] + b1)) ? 0x3F800000u : 0u;
                *(uint32_t*)(g_h16 + i0) = p;
                p  = (u01(rbits(ka, kb, i1))     < sigm(acc[mt][nf][2] + b0)) ? 0x3F80u : 0u;
                p |= (u01(rbits(ka, kb, i1 + 1)) < sigm(acc[mt][nf][3] + b1)) ? 0x3F800000u : 0u;
                *(uint32_t*)(g_h16 + i1) = p;
            } else {
                *(float2*)(Cf + i0) = make_float2(acc[mt][nf][0], acc[mt][nf][1]);
                *(float2*)(Cf + i1) = make_float2(acc[mt][nf][2], acc[mt][nf][3]);
            }
        }
    }
}

// ------------------------------ small kernels ------------------------------
__global__ void k_keys(const int* __restrict__ seed) {
    if (threadIdx.x != 0 || blockIdx.x != 0) return;
    uint32_t ck0 = 0u, ck1 = (uint32_t)seed[0], a, b, o0, o1;
    tf2x32(ck0, ck1, 0u, 0u, o0, o1);
    tf2x32(ck0, ck1, 0u, 1u, a, b);
    g_keys[0] = a; g_keys[1] = b; ck0 = o0; ck1 = o1;
    for (int t = 0; t < KSTEPS; t++) {
        uint32_t n0, n1;
        tf2x32(ck0, ck1, 0u, 0u, n0, n1);
        tf2x32(ck0, ck1, 0u, 1u, a, b); g_keys[2+6*t+0] = a; g_keys[2+6*t+1] = b;
        tf2x32(ck0, ck1, 0u, 2u, a, b); g_keys[2+6*t+2] = a; g_keys[2+6*t+3] = b;
        tf2x32(ck0, ck1, 0u, 3u, a, b); g_keys[2+6*t+4] = a; g_keys[2+6*t+5] = b;
        ck0 = n0; ck1 = n1;
    }
}

__global__ void k_cvt(const float* __restrict__ vd) {
    int i = blockIdx.x * 256 + threadIdx.x;
    __nv_bfloat16 x = __float2bfloat16(vd[i]);
    g_vd16[i] = x; g_v16[i] = x;
}

__global__ void k_split2(const float* __restrict__ W) {
    int i = blockIdx.x * 256 + threadIdx.x;
    float w = W[i];
    __nv_bfloat16 hi = __float2bfloat16(w);
    int v = i >> 10, k = i & 1023;
    g_B2[(size_t)v * 2048 + k] = hi;
    g_B2[(size_t)v * 2048 + 1024 + k] = __float2bfloat16(w - __bfloat162float(hi));
}

__global__ void k_split1(const float* __restrict__ W) {
    __shared__ float t[32][33];
    int x = blockIdx.x * 32 + threadIdx.x, y0 = blockIdx.y * 32;
    for (int j = threadIdx.y; j < 32; j += 8)
        t[j][threadIdx.x] = W[(size_t)(y0 + j) * 1024 + x];
    __syncthreads();
    for (int j = threadIdx.y; j < 32; j += 8) {
        float w = t[threadIdx.x][j];
        int h = blockIdx.x * 32 + j, v = y0 + threadIdx.x;
        __nv_bfloat16 hi = __float2bfloat16(w);
        g_B1[(size_t)h * 2048 + v] = hi;
        g_B1[(size_t)h * 2048 + 1024 + v] = __float2bfloat16(w - __bfloat162float(hi));
    }
}

__global__ void k_wcol(const float* __restrict__ W) {
    int h = blockIdx.x * 256 + threadIdx.x;
    float s = 0.0f;
    for (int v = 0; v < 1024; v++) s += W[(size_t)v * 1024 + h];
    g_wcol[h] = s;
}

__global__ void k_bsum(const float* __restrict__ b) {
    float s = 0.0f;
    for (int j = threadIdx.x; j < 1024; j += 256) s += b[j];
    __shared__ float sh[8];
    float w = warpSum(s);
    if ((threadIdx.x & 31) == 0) sh[threadIdx.x >> 5] = w;
    __syncthreads();
    if (threadIdx.x == 0) {
        float t = 0.0f;
        for (int k = 0; k < 8; k++) t += sh[k];
        g_bsum = t; g_acc[0] = 0.0; g_acc[1] = 0.0;
    }
}

__global__ void k_u0() {
    int i = blockIdx.x * 256 + threadIdx.x;
    g_u[i] = (u01(rbits(g_keys[0], g_keys[1], (uint32_t)i)) < 0.5f) ? 1.0f : 0.0f;
}

__global__ void k_vbranch0() {
    int i = blockIdx.x * 256 + threadIdx.x;
    float u = g_u[i >> 10];
    float v = __bfloat162float(g_v16[i]);
    g_A1[i] = __float2bfloat16((u != 0.0f) ? v : 1.0f - v);
}

// fused dE reduction + u sample + v update (one a-row pass)
__global__ __launch_bounds__(256) void k_dEvupd(const float* __restrict__ bb,
                                                int koffU, int koffV) {
    int row = blockIdx.x;
    const float* arow = g_a + (size_t)row * 1024;
    const __nv_bfloat16* vrow = g_v16 + (size_t)row * 1024;
    float av[4];
    float asum = 0.0f, va = 0.0f, vb = 0.0f;
#pragma unroll
    for (int k = 0; k < 4; k++) {
        int j = threadIdx.x + k * 256;
        av[k] = arow[j];
        float vv = __bfloat162float(vrow[j]);
        asum += av[k]; va += vv * av[k]; vb += vv * bb[j];
    }
    __shared__ float sh[3][8];
    __shared__ float su;
    float w0 = warpSum(asum), w1 = warpSum(va), w2 = warpSum(vb);
    int lane = threadIdx.x & 31, wd = threadIdx.x >> 5;
    if (lane == 0) { sh[0][wd] = w0; sh[1][wd] = w1; sh[2][wd] = w2; }
    __syncthreads();
    if (threadIdx.x == 0) {
        float A = 0, Va = 0, Vb = 0;
        for (int k = 0; k < 8; k++) { A += sh[0][k]; Va += sh[1][k]; Vb += sh[2][k]; }
        float dE = -g_bsum - A + 2.0f * Vb + 2.0f * Va;
        su = (u01(rbits(g_keys[koffU], g_keys[koffU + 1], (uint32_t)row)) < sigm(dE))
             ? 1.0f : 0.0f;
    }
    __syncthreads();
    float u = su;
    uint32_t ka = g_keys[koffV], kb = g_keys[koffV + 1];
#pragma unroll
    for (int k = 0; k < 4; k++) {
        int j = threadIdx.x + k * 256;
        float p = sigm(av[k] + bb[j]);
        uint32_t i = (uint32_t)row * 1024u + (uint32_t)j;
        float vn = (u01(rbits(ka, kb, i)) < p) ? 1.0f : 0.0f;
        g_A1[i] = __float2bfloat16(vn);
        g_v16[i] = __float2bfloat16((u != 0.0f) ? vn : 1.0f - vn);
    }
}

__global__ void k_fe(const __nv_bfloat16* __restrict__ v, const float* __restrict__ bb,
                     const float* __restrict__ cc, int accIdx) {
    int row = blockIdx.x;
    const float* srow = g_s + (size_t)row * 1024;
    const __nv_bfloat16* vrow = v + (size_t)row * 1024;
    float sp1 = 0.0f, sp2 = 0.0f, vb = 0.0f;
    for (int j = threadIdx.x; j < 1024; j += 256) {
        float s = srow[j];
        sp1 += softp(s + cc[j]);
        sp2 += softp(g_wcol[j] - s + cc[j]);
        vb += __bfloat162float(vrow[j]) * bb[j];
    }
    __shared__ float sh[3][8];
    float w0 = warpSum(sp1), w1 = warpSum(sp2), w2 = warpSum(vb);
    int lane = threadIdx.x & 31, wd = threadIdx.x >> 5;
    if (lane == 0) { sh[0][wd] = w0; sh[1][wd] = w1; sh[2][wd] = w2; }
    __syncthreads();
    if (threadIdx.x == 0) {
        float S1 = 0, S2 = 0, VB = 0;
        for (int k = 0; k < 8; k++) { S1 += sh[0][k]; S2 += sh[1][k]; VB += sh[2][k]; }
        float nfn = VB - S1, nff = (g_bsum - VB) - S2;
        float m = fmaxf(nfn, nff);
        float F = -(m + log1pf(expf(fminf(nfn, nff) - m)));
        atomicAdd(&g_acc[accIdx], (double)F);
    }
}

__global__ void k_final(float* __restrict__ out) {
    if (threadIdx.x == 0 && blockIdx.x == 0)
        out[0] = (float)((g_acc[0] - g_acc[1]) * (1.0 / (double)Bn));
}

// ------------------------------ launch -------------------------------------
extern "C" void kernel_launch(void* const* d_in, const int* in_sizes, int n_in,
                              void* d_out, int out_size) {
    const float* v_data = (const float*)d_in[0];
    const float* W      = (const float*)d_in[1];
    const float* b      = (const float*)d_in[2];
    const float* c      = (const float*)d_in[3];
    const int*   seed   = (const int*)d_in[4];
    float* out = (float*)d_out;

    __nv_bfloat16 *pA1, *pH, *pV, *pVd, *pB1, *pB2;
    float *pS, *pAa;
    cudaGetSymbolAddress((void**)&pA1, g_A1);
    cudaGetSymbolAddress((void**)&pH,  g_h16);
    cudaGetSymbolAddress((void**)&pV,  g_v16);
    cudaGetSymbolAddress((void**)&pVd, g_vd16);
    cudaGetSymbolAddress((void**)&pB1, g_B1);
    cudaGetSymbolAddress((void**)&pB2, g_B2);
    cudaGetSymbolAddress((void**)&pS,  g_s);
    cudaGetSymbolAddress((void**)&pAa, g_a);

    cudaFuncSetAttribute(k_mma<0>, cudaFuncAttributeMaxDynamicSharedMemorySize, SMEM_SZ);
    cudaFuncSetAttribute(k_mma<1>, cudaFuncAttributeMaxDynamicSharedMemorySize, SMEM_SZ);

    dim3 gg(8, 64);
    k_keys<<<1, 32>>>(seed);
    k_cvt<<<Bn * 1024 / 256, 256>>>(v_data);
    k_split2<<<1024 * 1024 / 256, 256>>>(W);
    k_split1<<<dim3(32, 32), dim3(32, 8)>>>(W);
    k_wcol<<<4, 256>>>(W);
    k_bsum<<<1, 256>>>(b);
    k_u0<<<Bn / 256, 256>>>();
    k_vbranch0<<<Bn * 1024 / 256, 256>>>();

    for (int t = 0; t < KSTEPS; t++) {
        int koff = 2 + 6 * t;
        k_mma<0><<<gg, 256, SMEM_SZ>>>(pA1, pB1, nullptr, c, koff);  // h = sample(vbr@W)
        k_mma<1><<<gg, 256, SMEM_SZ>>>(pH, pB2, pAa, nullptr, 0);    // a = h@W^T
        k_dEvupd<<<Bn, 256>>>(b, koff + 2, koff + 4);
    }

    k_mma<1><<<gg, 256, SMEM_SZ>>>(pVd, pB1, pS, nullptr, 0);
    k_fe<<<Bn, 256>>>(pVd, b, c, 0);
    k_mma<1><<<gg, 256, SMEM_SZ>>>(pV, pB1, pS, nullptr, 0);
    k_fe<<<Bn, 256>>>(pV, b, c, 1);
    k_final<<<1, 1>>>(out);
}